// round 1
// baseline (speedup 1.0000x reference)
#include <cuda_runtime.h>
#include <math.h>

// Problem constants
#define Bb 8
#define Tt 8192
#define Cc 512
#define Hh 8
#define Dd 64
#define NN (Bb*Tt)         // 65536 tokens
#define BH (Bb*Hh)         // 64
#define KV_SPLIT 8

// Scratch (device globals: allocation-free per harness rules)
__device__ float g_Q[(size_t)NN*Cc];
__device__ float g_K[(size_t)NN*Cc];
__device__ float g_V[(size_t)NN*Cc];
__device__ float g_Y[(size_t)NN*Cc];
__device__ float g_KV[(size_t)BH*Dd*Dd];
__device__ float g_Ksum[(size_t)BH*Dd];

// ---------------------------------------------------------------------------
// 128x128x8 register-blocked SGEMM:  out[n,c] = sum_k A[n,k]*W[c,k] + bias[c]
// act=1 applies elu(v)+1 = (v>0 ? v+1 : exp(v))
// A: [Nrows, Cc] row-major, W: [Cc, Cc] row-major (we use its rows => W^T GEMM)
// ---------------------------------------------------------------------------
__global__ __launch_bounds__(256) void sgemm_bias_act(
    const float* __restrict__ A, const float* __restrict__ W,
    const float* __restrict__ bias, float* __restrict__ out, int act)
{
    __shared__ float As[8][128];
    __shared__ float Bs[8][128];

    const int tid = threadIdx.x;
    const int bx = blockIdx.x;   // row tile (128 tokens)
    const int by = blockIdx.y;   // col tile (128 out features)

    const int loadRow = tid >> 1;        // 0..127
    const int loadCol = (tid & 1) * 4;   // 0 or 4

    const float* Ab = A + (size_t)bx * 128 * Cc;
    const float* Wb = W + (size_t)by * 128 * Cc;

    const int tx = tid & 15;   // 0..15 -> cols
    const int ty = tid >> 4;   // 0..15 -> rows

    float acc[8][8];
#pragma unroll
    for (int i = 0; i < 8; i++)
#pragma unroll
        for (int j = 0; j < 8; j++) acc[i][j] = 0.f;

    for (int k0 = 0; k0 < Cc; k0 += 8) {
        float4 av = *(const float4*)(Ab + (size_t)loadRow * Cc + k0 + loadCol);
        float4 wv = *(const float4*)(Wb + (size_t)loadRow * Cc + k0 + loadCol);
        As[loadCol + 0][loadRow] = av.x;
        As[loadCol + 1][loadRow] = av.y;
        As[loadCol + 2][loadRow] = av.z;
        As[loadCol + 3][loadRow] = av.w;
        Bs[loadCol + 0][loadRow] = wv.x;
        Bs[loadCol + 1][loadRow] = wv.y;
        Bs[loadCol + 2][loadRow] = wv.z;
        Bs[loadCol + 3][loadRow] = wv.w;
        __syncthreads();

#pragma unroll
        for (int k = 0; k < 8; k++) {
            float4 a0 = *(const float4*)&As[k][ty * 4];
            float4 a1 = *(const float4*)&As[k][64 + ty * 4];
            float4 b0 = *(const float4*)&Bs[k][tx * 4];
            float4 b1 = *(const float4*)&Bs[k][64 + tx * 4];
            float ra[8] = {a0.x, a0.y, a0.z, a0.w, a1.x, a1.y, a1.z, a1.w};
            float rb[8] = {b0.x, b0.y, b0.z, b0.w, b1.x, b1.y, b1.z, b1.w};
#pragma unroll
            for (int i = 0; i < 8; i++)
#pragma unroll
                for (int j = 0; j < 8; j++)
                    acc[i][j] = fmaf(ra[i], rb[j], acc[i][j]);
        }
        __syncthreads();
    }

#pragma unroll
    for (int i = 0; i < 8; i++) {
        int row = bx * 128 + ((i < 4) ? (ty * 4 + i) : (64 + ty * 4 + i - 4));
#pragma unroll
        for (int j = 0; j < 8; j++) {
            int col = by * 128 + ((j < 4) ? (tx * 4 + j) : (64 + tx * 4 + j - 4));
            float v = acc[i][j] + bias[col];
            if (act) v = (v > 0.f) ? (v + 1.f) : expf(v);
            out[(size_t)row * Cc + col] = v;
        }
    }
}

// ---------------------------------------------------------------------------
// Zero the KV / Ksum accumulators
// ---------------------------------------------------------------------------
__global__ void zero_kv()
{
    int i = blockIdx.x * blockDim.x + threadIdx.x;
    if (i < BH * Dd * Dd) g_KV[i] = 0.f;
    if (i < BH * Dd)      g_Ksum[i] = 0.f;
}

// ---------------------------------------------------------------------------
// KV[d][e] = sum_t K[t,d]*V[t,e];  Ksum[d] = sum_t K[t,d]   (per b,h)
// grid: (BH, KV_SPLIT), 256 threads. Atomic merge across splits.
// ---------------------------------------------------------------------------
__global__ __launch_bounds__(256) void kv_accum()
{
    const int bh = blockIdx.x;
    const int b = bh >> 3, h = bh & 7;
    const int tid = threadIdx.x;
    const int rows = Tt / KV_SPLIT;   // 1024
    const size_t base = ((size_t)b * Tt + (size_t)blockIdx.y * rows) * Cc + h * Dd;

    __shared__ float sK[8][64];
    __shared__ float sV[8][64];

    const int d0 = (tid >> 4) * 4;
    const int e0 = (tid & 15) * 4;

    float acc[4][4];
#pragma unroll
    for (int i = 0; i < 4; i++)
#pragma unroll
        for (int j = 0; j < 4; j++) acc[i][j] = 0.f;
    float ks = 0.f;

    for (int r0 = 0; r0 < rows; r0 += 8) {
#pragma unroll
        for (int i = 0; i < 2; i++) {
            int lin = tid + i * 256;
            int rr = lin >> 6, dd = lin & 63;
            size_t g = base + (size_t)(r0 + rr) * Cc + dd;
            sK[rr][dd] = g_K[g];
            sV[rr][dd] = g_V[g];
        }
        __syncthreads();
#pragma unroll
        for (int r = 0; r < 8; r++) {
            float k0 = sK[r][d0], k1 = sK[r][d0 + 1], k2 = sK[r][d0 + 2], k3 = sK[r][d0 + 3];
            float v0 = sV[r][e0], v1 = sV[r][e0 + 1], v2 = sV[r][e0 + 2], v3 = sV[r][e0 + 3];
            acc[0][0] = fmaf(k0, v0, acc[0][0]); acc[0][1] = fmaf(k0, v1, acc[0][1]);
            acc[0][2] = fmaf(k0, v2, acc[0][2]); acc[0][3] = fmaf(k0, v3, acc[0][3]);
            acc[1][0] = fmaf(k1, v0, acc[1][0]); acc[1][1] = fmaf(k1, v1, acc[1][1]);
            acc[1][2] = fmaf(k1, v2, acc[1][2]); acc[1][3] = fmaf(k1, v3, acc[1][3]);
            acc[2][0] = fmaf(k2, v0, acc[2][0]); acc[2][1] = fmaf(k2, v1, acc[2][1]);
            acc[2][2] = fmaf(k2, v2, acc[2][2]); acc[2][3] = fmaf(k2, v3, acc[2][3]);
            acc[3][0] = fmaf(k3, v0, acc[3][0]); acc[3][1] = fmaf(k3, v1, acc[3][1]);
            acc[3][2] = fmaf(k3, v2, acc[3][2]); acc[3][3] = fmaf(k3, v3, acc[3][3]);
        }
        if (tid < 64) {
#pragma unroll
            for (int r = 0; r < 8; r++) ks += sK[r][tid];
        }
        __syncthreads();
    }

    float* kvp = g_KV + (size_t)bh * Dd * Dd;
#pragma unroll
    for (int i = 0; i < 4; i++)
#pragma unroll
        for (int j = 0; j < 4; j++)
            atomicAdd(&kvp[(d0 + i) * Dd + (e0 + j)], acc[i][j]);
    if (tid < 64) atomicAdd(&g_Ksum[bh * Dd + tid], ks);
}

// ---------------------------------------------------------------------------
// Y[t, h*64+e] = (sum_d Q[t,d]*KV[d][e]) / (sum_d Q[t,d]*Ksum[d] + 1e-6)
// grid: (Tt/64, BH), 256 threads; 64 tokens/block, 4 threads/token x 16 e's.
// ---------------------------------------------------------------------------
__global__ __launch_bounds__(256) void y_kernel()
{
    const int bh = blockIdx.y;
    const int b = bh >> 3, h = bh & 7;
    const int t0 = blockIdx.x * 64;
    const int tid = threadIdx.x;

    __shared__ float sKV[64][64];
    __shared__ float sQ[64][65];
    __shared__ float sks[64];

    const float* kvp = g_KV + (size_t)bh * Dd * Dd;
#pragma unroll
    for (int i = 0; i < 16; i++) {
        int idx = tid + i * 256;
        sKV[idx >> 6][idx & 63] = kvp[idx];
    }
    if (tid < 64) sks[tid] = g_Ksum[bh * Dd + tid];
#pragma unroll
    for (int i = 0; i < 16; i++) {
        int idx = tid + i * 256;
        int r = idx >> 6, d = idx & 63;
        sQ[r][d] = g_Q[((size_t)b * Tt + t0 + r) * Cc + h * Dd + d];
    }
    __syncthreads();

    const int tok = tid >> 2;
    const int e0 = (tid & 3) * 16;

    float acc[16];
#pragma unroll
    for (int j = 0; j < 16; j++) acc[j] = 0.f;
    float nrm = 0.f;

#pragma unroll
    for (int d = 0; d < 64; d++) {
        float q = sQ[tok][d];
        nrm = fmaf(q, sks[d], nrm);
        const float4* kr = (const float4*)&sKV[d][e0];
        float4 c0 = kr[0], c1 = kr[1], c2 = kr[2], c3 = kr[3];
        acc[0]  = fmaf(q, c0.x, acc[0]);  acc[1]  = fmaf(q, c0.y, acc[1]);
        acc[2]  = fmaf(q, c0.z, acc[2]);  acc[3]  = fmaf(q, c0.w, acc[3]);
        acc[4]  = fmaf(q, c1.x, acc[4]);  acc[5]  = fmaf(q, c1.y, acc[5]);
        acc[6]  = fmaf(q, c1.z, acc[6]);  acc[7]  = fmaf(q, c1.w, acc[7]);
        acc[8]  = fmaf(q, c2.x, acc[8]);  acc[9]  = fmaf(q, c2.y, acc[9]);
        acc[10] = fmaf(q, c2.z, acc[10]); acc[11] = fmaf(q, c2.w, acc[11]);
        acc[12] = fmaf(q, c3.x, acc[12]); acc[13] = fmaf(q, c3.y, acc[13]);
        acc[14] = fmaf(q, c3.z, acc[14]); acc[15] = fmaf(q, c3.w, acc[15]);
    }

    float inv = 1.f / (nrm + 1e-6f);
    size_t ob = ((size_t)b * Tt + t0 + tok) * Cc + h * Dd + e0;
#pragma unroll
    for (int j = 0; j < 16; j++) g_Y[ob + j] = acc[j] * inv;
}

// ---------------------------------------------------------------------------
// Launch
// ---------------------------------------------------------------------------
extern "C" void kernel_launch(void* const* d_in, const int* in_sizes, int n_in,
                              void* d_out, int out_size)
{
    const float* x  = (const float*)d_in[0];
    const float* Wq = (const float*)d_in[1];
    const float* bq = (const float*)d_in[2];
    const float* Wk = (const float*)d_in[3];
    const float* bk = (const float*)d_in[4];
    const float* Wv = (const float*)d_in[5];
    const float* bv = (const float*)d_in[6];
    const float* Wo = (const float*)d_in[7];
    const float* bo = (const float*)d_in[8];
    float* out = (float*)d_out;

    static float *pQ = nullptr, *pK = nullptr, *pV = nullptr, *pY = nullptr;
    if (!pQ) {
        cudaGetSymbolAddress((void**)&pQ, g_Q);
        cudaGetSymbolAddress((void**)&pK, g_K);
        cudaGetSymbolAddress((void**)&pV, g_V);
        cudaGetSymbolAddress((void**)&pY, g_Y);
    }

    dim3 gg(NN / 128, Cc / 128);  // (512, 4)

    sgemm_bias_act<<<gg, 256>>>(x, Wq, bq, pQ, 1);   // Q = elu(xWq^T+bq)+1
    sgemm_bias_act<<<gg, 256>>>(x, Wk, bk, pK, 1);   // K = elu(xWk^T+bk)+1
    sgemm_bias_act<<<gg, 256>>>(x, Wv, bv, pV, 0);   // V = xWv^T+bv

    zero_kv<<<(BH * Dd * Dd + 255) / 256, 256>>>();
    kv_accum<<<dim3(BH, KV_SPLIT), 256>>>();
    y_kernel<<<dim3(Tt / 64, BH), 256>>>();

    sgemm_bias_act<<<gg, 256>>>(pY, Wo, bo, out, 0); // out = Y Wo^T + bo
}

// round 3
// speedup vs baseline: 2.0736x; 2.0736x over previous
#include <cuda_runtime.h>
#include <math.h>
#include <stdint.h>

// ---------------- Problem constants ----------------
#define Bb 8
#define Tt 8192
#define Cc 512
#define Hh 8
#define Dd 64
#define NN (Bb*Tt)         // 65536 tokens
#define BH (Bb*Hh)         // 64
#define KV_SPLIT 8

// ---------------- Scratch (device globals) ----------------
__device__ float g_Q[(size_t)NN*Cc];
__device__ float g_K[(size_t)NN*Cc];
__device__ float g_V[(size_t)NN*Cc];
__device__ float g_Y[(size_t)NN*Cc];
__device__ float g_Xc[(size_t)NN*Cc];       // tf32-rounded x
__device__ float g_Wc[(size_t)4*Cc*Cc];     // tf32-rounded Wq,Wk,Wv,Wo
__device__ float g_KV[(size_t)BH*Dd*Dd];
__device__ float g_Ksum[(size_t)BH*Dd];

// ---------------- helpers ----------------
__device__ __forceinline__ uint32_t smem_u32(const void* p) {
    uint32_t a;
    asm("{ .reg .u64 t; cvta.to.shared.u64 t, %1; cvt.u32.u64 %0, t; }" : "=r"(a) : "l"(p));
    return a;
}
__device__ __forceinline__ float rna_tf32(float v) {
    uint32_t u;
    asm("cvt.rna.tf32.f32 %0, %1;" : "=r"(u) : "f"(v));
    return __uint_as_float(u);
}

#define CP_ASYNC16(dst, src) \
    asm volatile("cp.async.cg.shared.global [%0], [%1], 16;" :: "r"(dst), "l"(src) : "memory")
#define CP_COMMIT() asm volatile("cp.async.commit_group;" ::: "memory")
#define CP_WAIT(n)  asm volatile("cp.async.wait_group %0;" :: "n"(n) : "memory")

__device__ __forceinline__ void ldsm_x4(uint32_t* r, uint32_t addr) {
    asm volatile("ldmatrix.sync.aligned.m8n8.x4.shared.b16 {%0,%1,%2,%3}, [%4];"
                 : "=r"(r[0]), "=r"(r[1]), "=r"(r[2]), "=r"(r[3]) : "r"(addr));
}
__device__ __forceinline__ void mma_tf32(float* c, const uint32_t* a, uint32_t b0, uint32_t b1) {
    asm volatile("mma.sync.aligned.m16n8k8.row.col.f32.tf32.tf32.f32 "
                 "{%0,%1,%2,%3},{%4,%5,%6,%7},{%8,%9},{%0,%1,%2,%3};"
                 : "+f"(c[0]), "+f"(c[1]), "+f"(c[2]), "+f"(c[3])
                 : "r"(a[0]), "r"(a[1]), "r"(a[2]), "r"(a[3]), "r"(b0), "r"(b1));
}

// ---------------- GEMM config ----------------
#define BM 128
#define BN 128
#define BK 32
#define NK (Cc / BK)        // 16
#define ASTR 36             // padded row stride in floats (conflict-free ldmatrix)
#define TILE_FLOATS (BM * ASTR)          // 4608 per operand
#define STAGE_FLOATS (2 * TILE_FLOATS)   // A + B
#define GEMM_SMEM (2 * STAGE_FLOATS * 4) // 73728 bytes

// out[m, n] = sum_k A[m,k]*B[n,k] + bias[n]; act=1 -> elu(v)+1
__global__ __launch_bounds__(256, 1)
void gemm_tf32(const float* __restrict__ A, const float* __restrict__ B,
               const float* __restrict__ bias, float* __restrict__ out, int act)
{
    extern __shared__ float sm[];
    const int tid = threadIdx.x;
    const int wid = tid >> 5;
    const int lane = tid & 31;
    const int m0 = blockIdx.x * BM;
    const int n0 = blockIdx.y * BN;

    const int wr = wid >> 2;          // 0..1 -> 64-row slab
    const int wc = wid & 3;           // 0..3 -> 32-col slab
    const int m_warp = wr * 64;
    const int n_warp = wc * 32;

    // ldmatrix per-thread source row/col (within A tile)
    const int lm_row = (lane & 7) + ((lane >> 3) & 1) * 8;
    const int lm_cb  = ((lane >> 4) & 1) * 16;   // byte offset (tf32 cols 0-3 vs 4-7)
    // B scalar fragment coords
    const int b_row = lane >> 2;       // n offset within 8
    const int b_col = lane & 3;        // k offset within 4

    const uint32_t sm_base = smem_u32(sm);

    float acc[4][4][4];
#pragma unroll
    for (int i = 0; i < 4; i++)
#pragma unroll
        for (int j = 0; j < 4; j++)
#pragma unroll
            for (int k = 0; k < 4; k++) acc[i][j][k] = 0.f;

    // global load assignment: 1024 float4 per operand tile, 4 per thread
    const int g_row = tid >> 1;              // reuse pattern below instead
    (void)g_row;

    auto load_stage = [&](int kc, int s) {
        float* sA = sm + s * STAGE_FLOATS;
        float* sB = sA + TILE_FLOATS;
        const float* gA = A + (size_t)(m0) * Cc + kc * BK;
        const float* gB = B + (size_t)(n0) * Cc + kc * BK;
        uint32_t dA = smem_u32(sA);
        uint32_t dB = smem_u32(sB);
#pragma unroll
        for (int i = 0; i < 4; i++) {
            int idx = tid + i * 256;         // 0..1023
            int row = idx >> 3;
            int c4 = idx & 7;
            CP_ASYNC16(dA + (row * ASTR + c4 * 4) * 4, gA + (size_t)row * Cc + c4 * 4);
        }
#pragma unroll
        for (int i = 0; i < 4; i++) {
            int idx = tid + i * 256;
            int row = idx >> 3;
            int c4 = idx & 7;
            CP_ASYNC16(dB + (row * ASTR + c4 * 4) * 4, gB + (size_t)row * Cc + c4 * 4);
        }
        CP_COMMIT();
    };

    load_stage(0, 0);

    for (int kt = 0; kt < NK; kt++) {
        if (kt + 1 < NK) {
            load_stage(kt + 1, (kt + 1) & 1);
            CP_WAIT(1);
        } else {
            CP_WAIT(0);
        }
        __syncthreads();

        const int s = kt & 1;
        const float* sA = sm + s * STAGE_FLOATS;
        const float* sB = sA + TILE_FLOATS;
        const uint32_t aBase = sm_base + (uint32_t)(s * STAGE_FLOATS) * 4;

#pragma unroll
        for (int ks = 0; ks < 4; ks++) {
            uint32_t af[4][4];
#pragma unroll
            for (int mi = 0; mi < 4; mi++) {
                uint32_t addr = aBase
                    + (uint32_t)((m_warp + mi * 16 + lm_row) * ASTR) * 4
                    + lm_cb + ks * 32;
                ldsm_x4(af[mi], addr);
            }
            uint32_t bf[4][2];
#pragma unroll
            for (int nj = 0; nj < 4; nj++) {
                const float* bp = sB + (size_t)(n_warp + nj * 8 + b_row) * ASTR + ks * 8 + b_col;
                bf[nj][0] = __float_as_uint(bp[0]);
                bf[nj][1] = __float_as_uint(bp[4]);
            }
#pragma unroll
            for (int mi = 0; mi < 4; mi++)
#pragma unroll
                for (int nj = 0; nj < 4; nj++)
                    mma_tf32(acc[mi][nj], af[mi], bf[nj][0], bf[nj][1]);
        }
        __syncthreads();
    }

    // ---- epilogue: direct global store with bias + activation ----
    const int r_lo = lane >> 2;          // 0..7
    const int c_off = (lane & 3) * 2;    // 0,2,4,6
#pragma unroll
    for (int mi = 0; mi < 4; mi++) {
#pragma unroll
        for (int nj = 0; nj < 4; nj++) {
            int col = n0 + n_warp + nj * 8 + c_off;
            float b0 = bias[col], b1 = bias[col + 1];
#pragma unroll
            for (int half = 0; half < 2; half++) {
                int row = m0 + m_warp + mi * 16 + r_lo + half * 8;
                float v0 = acc[mi][nj][half * 2 + 0] + b0;
                float v1 = acc[mi][nj][half * 2 + 1] + b1;
                if (act) {
                    v0 = (v0 > 0.f) ? v0 + 1.f : expf(v0);
                    v1 = (v1 > 0.f) ? v1 + 1.f : expf(v1);
                }
                float2 v = make_float2(v0, v1);
                *(float2*)(out + (size_t)row * Cc + col) = v;
            }
        }
    }
}

// ---------------- tf32 (RNA) rounding pass ----------------
__global__ __launch_bounds__(256) void cvt_tf32(const float4* __restrict__ src,
                                                float4* __restrict__ dst, int n4)
{
    int i = blockIdx.x * blockDim.x + threadIdx.x;
    if (i < n4) {
        float4 v = src[i];
        v.x = rna_tf32(v.x); v.y = rna_tf32(v.y);
        v.z = rna_tf32(v.z); v.w = rna_tf32(v.w);
        dst[i] = v;
    }
}

// ---------------- attention-side kernels ----------------
__global__ void zero_kv()
{
    int i = blockIdx.x * blockDim.x + threadIdx.x;
    if (i < BH * Dd * Dd) g_KV[i] = 0.f;
    if (i < BH * Dd)      g_Ksum[i] = 0.f;
}

__global__ __launch_bounds__(256) void kv_accum()
{
    const int bh = blockIdx.x;
    const int b = bh >> 3, h = bh & 7;
    const int tid = threadIdx.x;
    const int rows = Tt / KV_SPLIT;
    const size_t base = ((size_t)b * Tt + (size_t)blockIdx.y * rows) * Cc + h * Dd;

    __shared__ float sK[8][64];
    __shared__ float sV[8][64];

    const int d0 = (tid >> 4) * 4;
    const int e0 = (tid & 15) * 4;

    float acc[4][4];
#pragma unroll
    for (int i = 0; i < 4; i++)
#pragma unroll
        for (int j = 0; j < 4; j++) acc[i][j] = 0.f;
    float ks = 0.f;

    for (int r0 = 0; r0 < rows; r0 += 8) {
#pragma unroll
        for (int i = 0; i < 2; i++) {
            int lin = tid + i * 256;
            int rr = lin >> 6, dd = lin & 63;
            size_t g = base + (size_t)(r0 + rr) * Cc + dd;
            sK[rr][dd] = g_K[g];
            sV[rr][dd] = g_V[g];
        }
        __syncthreads();
#pragma unroll
        for (int r = 0; r < 8; r++) {
            float k0 = sK[r][d0], k1 = sK[r][d0 + 1], k2 = sK[r][d0 + 2], k3 = sK[r][d0 + 3];
            float v0 = sV[r][e0], v1 = sV[r][e0 + 1], v2 = sV[r][e0 + 2], v3 = sV[r][e0 + 3];
            acc[0][0] = fmaf(k0, v0, acc[0][0]); acc[0][1] = fmaf(k0, v1, acc[0][1]);
            acc[0][2] = fmaf(k0, v2, acc[0][2]); acc[0][3] = fmaf(k0, v3, acc[0][3]);
            acc[1][0] = fmaf(k1, v0, acc[1][0]); acc[1][1] = fmaf(k1, v1, acc[1][1]);
            acc[1][2] = fmaf(k1, v2, acc[1][2]); acc[1][3] = fmaf(k1, v3, acc[1][3]);
            acc[2][0] = fmaf(k2, v0, acc[2][0]); acc[2][1] = fmaf(k2, v1, acc[2][1]);
            acc[2][2] = fmaf(k2, v2, acc[2][2]); acc[2][3] = fmaf(k2, v3, acc[2][3]);
            acc[3][0] = fmaf(k3, v0, acc[3][0]); acc[3][1] = fmaf(k3, v1, acc[3][1]);
            acc[3][2] = fmaf(k3, v2, acc[3][2]); acc[3][3] = fmaf(k3, v3, acc[3][3]);
        }
        if (tid < 64) {
#pragma unroll
            for (int r = 0; r < 8; r++) ks += sK[r][tid];
        }
        __syncthreads();
    }

    float* kvp = g_KV + (size_t)bh * Dd * Dd;
#pragma unroll
    for (int i = 0; i < 4; i++)
#pragma unroll
        for (int j = 0; j < 4; j++)
            atomicAdd(&kvp[(d0 + i) * Dd + (e0 + j)], acc[i][j]);
    if (tid < 64) atomicAdd(&g_Ksum[bh * Dd + tid], ks);
}

__global__ __launch_bounds__(256) void y_kernel()
{
    const int bh = blockIdx.y;
    const int b = bh >> 3, h = bh & 7;
    const int t0 = blockIdx.x * 64;
    const int tid = threadIdx.x;

    __shared__ float sKV[64][64];
    __shared__ float sQ[64][65];
    __shared__ float sks[64];

    const float* kvp = g_KV + (size_t)bh * Dd * Dd;
#pragma unroll
    for (int i = 0; i < 16; i++) {
        int idx = tid + i * 256;
        sKV[idx >> 6][idx & 63] = kvp[idx];
    }
    if (tid < 64) sks[tid] = g_Ksum[bh * Dd + tid];
#pragma unroll
    for (int i = 0; i < 16; i++) {
        int idx = tid + i * 256;
        int r = idx >> 6, d = idx & 63;
        sQ[r][d] = g_Q[((size_t)b * Tt + t0 + r) * Cc + h * Dd + d];
    }
    __syncthreads();

    const int tok = tid >> 2;
    const int e0 = (tid & 3) * 16;

    float acc[16];
#pragma unroll
    for (int j = 0; j < 16; j++) acc[j] = 0.f;
    float nrm = 0.f;

#pragma unroll
    for (int d = 0; d < 64; d++) {
        float q = sQ[tok][d];
        nrm = fmaf(q, sks[d], nrm);
        const float4* kr = (const float4*)&sKV[d][e0];
        float4 c0 = kr[0], c1 = kr[1], c2 = kr[2], c3 = kr[3];
        acc[0]  = fmaf(q, c0.x, acc[0]);  acc[1]  = fmaf(q, c0.y, acc[1]);
        acc[2]  = fmaf(q, c0.z, acc[2]);  acc[3]  = fmaf(q, c0.w, acc[3]);
        acc[4]  = fmaf(q, c1.x, acc[4]);  acc[5]  = fmaf(q, c1.y, acc[5]);
        acc[6]  = fmaf(q, c1.z, acc[6]);  acc[7]  = fmaf(q, c1.w, acc[7]);
        acc[8]  = fmaf(q, c2.x, acc[8]);  acc[9]  = fmaf(q, c2.y, acc[9]);
        acc[10] = fmaf(q, c2.z, acc[10]); acc[11] = fmaf(q, c2.w, acc[11]);
        acc[12] = fmaf(q, c3.x, acc[12]); acc[13] = fmaf(q, c3.y, acc[13]);
        acc[14] = fmaf(q, c3.z, acc[14]); acc[15] = fmaf(q, c3.w, acc[15]);
    }

    float inv = 1.f / (nrm + 1e-6f);
    size_t ob = ((size_t)b * Tt + t0 + tok) * Cc + h * Dd + e0;
#pragma unroll
    for (int j = 0; j < 16; j++) g_Y[ob + j] = rna_tf32(acc[j] * inv);  // tf32 for O-GEMM
}

// ---------------- launch ----------------
extern "C" void kernel_launch(void* const* d_in, const int* in_sizes, int n_in,
                              void* d_out, int out_size)
{
    const float* x  = (const float*)d_in[0];
    const float* Wq = (const float*)d_in[1];
    const float* bq = (const float*)d_in[2];
    const float* Wk = (const float*)d_in[3];
    const float* bk = (const float*)d_in[4];
    const float* Wv = (const float*)d_in[5];
    const float* bv = (const float*)d_in[6];
    const float* Wo = (const float*)d_in[7];
    const float* bo = (const float*)d_in[8];
    float* out = (float*)d_out;

    static float *pQ = nullptr, *pK, *pV, *pY, *pXc, *pWc;
    static bool inited = false;
    if (!inited) {
        cudaGetSymbolAddress((void**)&pQ, g_Q);
        cudaGetSymbolAddress((void**)&pK, g_K);
        cudaGetSymbolAddress((void**)&pV, g_V);
        cudaGetSymbolAddress((void**)&pY, g_Y);
        cudaGetSymbolAddress((void**)&pXc, g_Xc);
        cudaGetSymbolAddress((void**)&pWc, g_Wc);
        cudaFuncSetAttribute(gemm_tf32, cudaFuncAttributeMaxDynamicSharedMemorySize, GEMM_SMEM);
        inited = true;
    }

    // tf32 RNA rounding of GEMM inputs
    const float* Ws[4] = {Wq, Wk, Wv, Wo};
    {
        int n4 = NN * Cc / 4;
        cvt_tf32<<<n4 / 256, 256>>>((const float4*)x, (float4*)pXc, n4);
        int w4 = Cc * Cc / 4;
        for (int i = 0; i < 4; i++)
            cvt_tf32<<<w4 / 256, 256>>>((const float4*)Ws[i], (float4*)(pWc + (size_t)i * Cc * Cc), w4);
    }

    dim3 gg(NN / BM, Cc / BN);   // (512, 4)

    gemm_tf32<<<gg, 256, GEMM_SMEM>>>(pXc, pWc + 0 * (size_t)Cc * Cc, bq, pQ, 1);
    gemm_tf32<<<gg, 256, GEMM_SMEM>>>(pXc, pWc + 1 * (size_t)Cc * Cc, bk, pK, 1);
    gemm_tf32<<<gg, 256, GEMM_SMEM>>>(pXc, pWc + 2 * (size_t)Cc * Cc, bv, pV, 0);

    zero_kv<<<(BH * Dd * Dd + 255) / 256, 256>>>();
    kv_accum<<<dim3(BH, KV_SPLIT), 256>>>();
    y_kernel<<<dim3(Tt / 64, BH), 256>>>();

    gemm_tf32<<<gg, 256, GEMM_SMEM>>>(pY, pWc + 3 * (size_t)Cc * Cc, bo, out, 0);
}

// round 4
// speedup vs baseline: 2.4473x; 1.1802x over previous
#include <cuda_runtime.h>
#include <math.h>
#include <stdint.h>

// ---------------- Problem constants ----------------
#define Bb 8
#define Tt 8192
#define Cc 512
#define Hh 8
#define Dd 64
#define NN (Bb*Tt)         // 65536 tokens
#define BH (Bb*Hh)         // 64
#define KV_SPLIT 8

// ---------------- Scratch (device globals) ----------------
__device__ float g_Q[(size_t)NN*Cc];
__device__ float g_K[(size_t)NN*Cc];
__device__ float g_V[(size_t)NN*Cc];
__device__ float g_Y[(size_t)NN*Cc];
__device__ float g_Xc[(size_t)NN*Cc];       // tf32-rounded x
__device__ float g_Wc[(size_t)4*Cc*Cc];     // tf32-rounded Wq,Wk,Wv,Wo
__device__ float g_KV[(size_t)BH*Dd*Dd];
__device__ float g_Ksum[(size_t)BH*Dd];

// ---------------- helpers ----------------
__device__ __forceinline__ uint32_t smem_u32(const void* p) {
    uint32_t a;
    asm("{ .reg .u64 t; cvta.to.shared.u64 t, %1; cvt.u32.u64 %0, t; }" : "=r"(a) : "l"(p));
    return a;
}
__device__ __forceinline__ float rna_tf32(float v) {
    uint32_t u;
    asm("cvt.rna.tf32.f32 %0, %1;" : "=r"(u) : "f"(v));
    return __uint_as_float(u);
}

#define CP_ASYNC16(dst, src) \
    asm volatile("cp.async.cg.shared.global [%0], [%1], 16;" :: "r"(dst), "l"(src) : "memory")
#define CP_COMMIT() asm volatile("cp.async.commit_group;" ::: "memory")
#define CP_WAIT(n)  asm volatile("cp.async.wait_group %0;" :: "n"(n) : "memory")

__device__ __forceinline__ void ldsm_x4(uint32_t* r, uint32_t addr) {
    asm volatile("ldmatrix.sync.aligned.m8n8.x4.shared.b16 {%0,%1,%2,%3}, [%4];"
                 : "=r"(r[0]), "=r"(r[1]), "=r"(r[2]), "=r"(r[3]) : "r"(addr));
}
__device__ __forceinline__ void mma_tf32(float* c, const uint32_t* a, uint32_t b0, uint32_t b1) {
    asm volatile("mma.sync.aligned.m16n8k8.row.col.f32.tf32.tf32.f32 "
                 "{%0,%1,%2,%3},{%4,%5,%6,%7},{%8,%9},{%0,%1,%2,%3};"
                 : "+f"(c[0]), "+f"(c[1]), "+f"(c[2]), "+f"(c[3])
                 : "r"(a[0]), "r"(a[1]), "r"(a[2]), "r"(a[3]), "r"(b0), "r"(b1));
}

// ---------------- GEMM config ----------------
#define BM 128
#define BN 128
#define BK 32
#define NK (Cc / BK)        // 16
#define ASTR 36             // padded row stride in floats (conflict-free ldmatrix)
#define TILE_FLOATS (BM * ASTR)          // 4608 per operand
#define STAGE_FLOATS (2 * TILE_FLOATS)   // A + B
#define GEMM_SMEM (2 * STAGE_FLOATS * 4) // 73728 bytes

// out[m, n] = sum_k A[m,k]*B[n,k] + bias[n]; act=1 -> elu(v)+1
__global__ __launch_bounds__(256, 2)
void gemm_tf32(const float* __restrict__ A, const float* __restrict__ B,
               const float* __restrict__ bias, float* __restrict__ out, int act)
{
    extern __shared__ float sm[];
    const int tid = threadIdx.x;
    const int wid = tid >> 5;
    const int lane = tid & 31;
    const int m0 = blockIdx.x * BM;
    const int n0 = blockIdx.y * BN;

    const int wr = wid >> 2;          // 0..1 -> 64-row slab
    const int wc = wid & 3;           // 0..3 -> 32-col slab
    const int m_warp = wr * 64;
    const int n_warp = wc * 32;

    // A ldmatrix per-thread source row/col (within A tile)
    const int lm_row = (lane & 7) + ((lane >> 3) & 1) * 8;
    const int lm_cb  = ((lane >> 4) & 1) * 16;   // byte offset (tf32 cols 0-3 vs 4-7)
    // B ldmatrix addressing: 4 matrix groups
    const int bg = lane >> 3;         // 0..3
    const int br = lane & 7;          // row within group
    // groups 0,1 -> nj even (rows +0), byte off 0/16; groups 2,3 -> nj odd (+8 rows)
    const int b_row_off = (bg >> 1) * 8 + br;    // row within 16-row nj-pair
    const int b_byte_off = (bg & 1) * 16;

    const uint32_t sm_base = smem_u32(sm);

    float acc[4][4][4];
#pragma unroll
    for (int i = 0; i < 4; i++)
#pragma unroll
        for (int j = 0; j < 4; j++)
#pragma unroll
            for (int k = 0; k < 4; k++) acc[i][j][k] = 0.f;

    auto load_stage = [&](int kc, int s) {
        float* sA = sm + s * STAGE_FLOATS;
        float* sB = sA + TILE_FLOATS;
        const float* gA = A + (size_t)(m0) * Cc + kc * BK;
        const float* gB = B + (size_t)(n0) * Cc + kc * BK;
        uint32_t dA = smem_u32(sA);
        uint32_t dB = smem_u32(sB);
#pragma unroll
        for (int i = 0; i < 4; i++) {
            int idx = tid + i * 256;         // 0..1023
            int row = idx >> 3;
            int c4 = idx & 7;
            CP_ASYNC16(dA + (row * ASTR + c4 * 4) * 4, gA + (size_t)row * Cc + c4 * 4);
        }
#pragma unroll
        for (int i = 0; i < 4; i++) {
            int idx = tid + i * 256;
            int row = idx >> 3;
            int c4 = idx & 7;
            CP_ASYNC16(dB + (row * ASTR + c4 * 4) * 4, gB + (size_t)row * Cc + c4 * 4);
        }
        CP_COMMIT();
    };

    load_stage(0, 0);

    for (int kt = 0; kt < NK; kt++) {
        if (kt + 1 < NK) {
            load_stage(kt + 1, (kt + 1) & 1);
            CP_WAIT(1);
        } else {
            CP_WAIT(0);
        }
        __syncthreads();

        const int s = kt & 1;
        const uint32_t aBase = sm_base + (uint32_t)(s * STAGE_FLOATS) * 4
                             + (uint32_t)((m_warp + lm_row) * ASTR) * 4 + lm_cb;
        const uint32_t bBase = sm_base + (uint32_t)(s * STAGE_FLOATS + TILE_FLOATS) * 4
                             + (uint32_t)((n_warp + b_row_off) * ASTR) * 4 + b_byte_off;

#pragma unroll
        for (int ks = 0; ks < 4; ks++) {
            uint32_t af[4][4];
#pragma unroll
            for (int mi = 0; mi < 4; mi++)
                ldsm_x4(af[mi], aBase + (uint32_t)(mi * 16 * ASTR) * 4 + ks * 32);

            uint32_t bf[2][4];   // [nj pair][b0_lo, b1_lo, b0_hi, b1_hi]
#pragma unroll
            for (int p = 0; p < 2; p++)
                ldsm_x4(bf[p], bBase + (uint32_t)(p * 16 * ASTR) * 4 + ks * 32);

#pragma unroll
            for (int mi = 0; mi < 4; mi++) {
#pragma unroll
                for (int p = 0; p < 2; p++) {
                    mma_tf32(acc[mi][p * 2 + 0], af[mi], bf[p][0], bf[p][1]);
                    mma_tf32(acc[mi][p * 2 + 1], af[mi], bf[p][2], bf[p][3]);
                }
            }
        }
        __syncthreads();
    }

    // ---- epilogue: direct global store with bias + activation ----
    const int r_lo = lane >> 2;          // 0..7
    const int c_off = (lane & 3) * 2;    // 0,2,4,6
#pragma unroll
    for (int mi = 0; mi < 4; mi++) {
#pragma unroll
        for (int nj = 0; nj < 4; nj++) {
            int col = n0 + n_warp + nj * 8 + c_off;
            float b0 = bias[col], b1 = bias[col + 1];
#pragma unroll
            for (int half = 0; half < 2; half++) {
                int row = m0 + m_warp + mi * 16 + r_lo + half * 8;
                float v0 = acc[mi][nj][half * 2 + 0] + b0;
                float v1 = acc[mi][nj][half * 2 + 1] + b1;
                if (act) {
                    v0 = (v0 > 0.f) ? v0 + 1.f : expf(v0);
                    v1 = (v1 > 0.f) ? v1 + 1.f : expf(v1);
                }
                float2 v = make_float2(v0, v1);
                *(float2*)(out + (size_t)row * Cc + col) = v;
            }
        }
    }
}

// ---------------- tf32 (RNA) rounding pass ----------------
__global__ __launch_bounds__(256) void cvt_tf32(const float4* __restrict__ src,
                                                float4* __restrict__ dst, int n4)
{
    int i = blockIdx.x * blockDim.x + threadIdx.x;
    if (i < n4) {
        float4 v = src[i];
        v.x = rna_tf32(v.x); v.y = rna_tf32(v.y);
        v.z = rna_tf32(v.z); v.w = rna_tf32(v.w);
        dst[i] = v;
    }
}

// ---------------- attention-side kernels ----------------
__global__ void zero_kv()
{
    int i = blockIdx.x * blockDim.x + threadIdx.x;
    if (i < BH * Dd * Dd) g_KV[i] = 0.f;
    if (i < BH * Dd)      g_Ksum[i] = 0.f;
}

__global__ __launch_bounds__(256) void kv_accum()
{
    const int bh = blockIdx.x;
    const int b = bh >> 3, h = bh & 7;
    const int tid = threadIdx.x;
    const int rows = Tt / KV_SPLIT;
    const size_t base = ((size_t)b * Tt + (size_t)blockIdx.y * rows) * Cc + h * Dd;

    __shared__ float sK[8][64];
    __shared__ float sV[8][64];

    const int d0 = (tid >> 4) * 4;
    const int e0 = (tid & 15) * 4;

    float acc[4][4];
#pragma unroll
    for (int i = 0; i < 4; i++)
#pragma unroll
        for (int j = 0; j < 4; j++) acc[i][j] = 0.f;
    float ks = 0.f;

    for (int r0 = 0; r0 < rows; r0 += 8) {
#pragma unroll
        for (int i = 0; i < 2; i++) {
            int lin = tid + i * 256;
            int rr = lin >> 6, dd = lin & 63;
            size_t g = base + (size_t)(r0 + rr) * Cc + dd;
            sK[rr][dd] = g_K[g];
            sV[rr][dd] = g_V[g];
        }
        __syncthreads();
#pragma unroll
        for (int r = 0; r < 8; r++) {
            float k0 = sK[r][d0], k1 = sK[r][d0 + 1], k2 = sK[r][d0 + 2], k3 = sK[r][d0 + 3];
            float v0 = sV[r][e0], v1 = sV[r][e0 + 1], v2 = sV[r][e0 + 2], v3 = sV[r][e0 + 3];
            acc[0][0] = fmaf(k0, v0, acc[0][0]); acc[0][1] = fmaf(k0, v1, acc[0][1]);
            acc[0][2] = fmaf(k0, v2, acc[0][2]); acc[0][3] = fmaf(k0, v3, acc[0][3]);
            acc[1][0] = fmaf(k1, v0, acc[1][0]); acc[1][1] = fmaf(k1, v1, acc[1][1]);
            acc[1][2] = fmaf(k1, v2, acc[1][2]); acc[1][3] = fmaf(k1, v3, acc[1][3]);
            acc[2][0] = fmaf(k2, v0, acc[2][0]); acc[2][1] = fmaf(k2, v1, acc[2][1]);
            acc[2][2] = fmaf(k2, v2, acc[2][2]); acc[2][3] = fmaf(k2, v3, acc[2][3]);
            acc[3][0] = fmaf(k3, v0, acc[3][0]); acc[3][1] = fmaf(k3, v1, acc[3][1]);
            acc[3][2] = fmaf(k3, v2, acc[3][2]); acc[3][3] = fmaf(k3, v3, acc[3][3]);
        }
        if (tid < 64) {
#pragma unroll
            for (int r = 0; r < 8; r++) ks += sK[r][tid];
        }
        __syncthreads();
    }

    float* kvp = g_KV + (size_t)bh * Dd * Dd;
#pragma unroll
    for (int i = 0; i < 4; i++)
#pragma unroll
        for (int j = 0; j < 4; j++)
            atomicAdd(&kvp[(d0 + i) * Dd + (e0 + j)], acc[i][j]);
    if (tid < 64) atomicAdd(&g_Ksum[bh * Dd + tid], ks);
}

__global__ __launch_bounds__(256) void y_kernel()
{
    const int bh = blockIdx.y;
    const int b = bh >> 3, h = bh & 7;
    const int t0 = blockIdx.x * 64;
    const int tid = threadIdx.x;

    __shared__ float sKV[64][64];
    __shared__ float sQ[64][65];
    __shared__ float sks[64];

    const float* kvp = g_KV + (size_t)bh * Dd * Dd;
#pragma unroll
    for (int i = 0; i < 16; i++) {
        int idx = tid + i * 256;
        sKV[idx >> 6][idx & 63] = kvp[idx];
    }
    if (tid < 64) sks[tid] = g_Ksum[bh * Dd + tid];
#pragma unroll
    for (int i = 0; i < 16; i++) {
        int idx = tid + i * 256;
        int r = idx >> 6, d = idx & 63;
        sQ[r][d] = g_Q[((size_t)b * Tt + t0 + r) * Cc + h * Dd + d];
    }
    __syncthreads();

    const int tok = tid >> 2;
    const int e0 = (tid & 3) * 16;

    float acc[16];
#pragma unroll
    for (int j = 0; j < 16; j++) acc[j] = 0.f;
    float nrm = 0.f;

#pragma unroll
    for (int d = 0; d < 64; d++) {
        float q = sQ[tok][d];
        nrm = fmaf(q, sks[d], nrm);
        const float4* kr = (const float4*)&sKV[d][e0];
        float4 c0 = kr[0], c1 = kr[1], c2 = kr[2], c3 = kr[3];
        acc[0]  = fmaf(q, c0.x, acc[0]);  acc[1]  = fmaf(q, c0.y, acc[1]);
        acc[2]  = fmaf(q, c0.z, acc[2]);  acc[3]  = fmaf(q, c0.w, acc[3]);
        acc[4]  = fmaf(q, c1.x, acc[4]);  acc[5]  = fmaf(q, c1.y, acc[5]);
        acc[6]  = fmaf(q, c1.z, acc[6]);  acc[7]  = fmaf(q, c1.w, acc[7]);
        acc[8]  = fmaf(q, c2.x, acc[8]);  acc[9]  = fmaf(q, c2.y, acc[9]);
        acc[10] = fmaf(q, c2.z, acc[10]); acc[11] = fmaf(q, c2.w, acc[11]);
        acc[12] = fmaf(q, c3.x, acc[12]); acc[13] = fmaf(q, c3.y, acc[13]);
        acc[14] = fmaf(q, c3.z, acc[14]); acc[15] = fmaf(q, c3.w, acc[15]);
    }

    float inv = 1.f / (nrm + 1e-6f);
    size_t ob = ((size_t)b * Tt + t0 + tok) * Cc + h * Dd + e0;
#pragma unroll
    for (int j = 0; j < 16; j++) g_Y[ob + j] = rna_tf32(acc[j] * inv);  // tf32 for O-GEMM
}

// ---------------- launch ----------------
extern "C" void kernel_launch(void* const* d_in, const int* in_sizes, int n_in,
                              void* d_out, int out_size)
{
    const float* x  = (const float*)d_in[0];
    const float* Wq = (const float*)d_in[1];
    const float* bq = (const float*)d_in[2];
    const float* Wk = (const float*)d_in[3];
    const float* bk = (const float*)d_in[4];
    const float* Wv = (const float*)d_in[5];
    const float* bv = (const float*)d_in[6];
    const float* Wo = (const float*)d_in[7];
    const float* bo = (const float*)d_in[8];
    float* out = (float*)d_out;

    static float *pQ = nullptr, *pK, *pV, *pY, *pXc, *pWc;
    static bool inited = false;
    if (!inited) {
        cudaGetSymbolAddress((void**)&pQ, g_Q);
        cudaGetSymbolAddress((void**)&pK, g_K);
        cudaGetSymbolAddress((void**)&pV, g_V);
        cudaGetSymbolAddress((void**)&pY, g_Y);
        cudaGetSymbolAddress((void**)&pXc, g_Xc);
        cudaGetSymbolAddress((void**)&pWc, g_Wc);
        cudaFuncSetAttribute(gemm_tf32, cudaFuncAttributeMaxDynamicSharedMemorySize, GEMM_SMEM);
        inited = true;
    }

    // tf32 RNA rounding of GEMM inputs
    const float* Ws[4] = {Wq, Wk, Wv, Wo};
    {
        int n4 = NN * Cc / 4;
        cvt_tf32<<<n4 / 256, 256>>>((const float4*)x, (float4*)pXc, n4);
        int w4 = Cc * Cc / 4;
        for (int i = 0; i < 4; i++)
            cvt_tf32<<<w4 / 256, 256>>>((const float4*)Ws[i], (float4*)(pWc + (size_t)i * Cc * Cc), w4);
    }

    dim3 gg(NN / BM, Cc / BN);   // (512, 4)

    gemm_tf32<<<gg, 256, GEMM_SMEM>>>(pXc, pWc + 0 * (size_t)Cc * Cc, bq, pQ, 1);
    gemm_tf32<<<gg, 256, GEMM_SMEM>>>(pXc, pWc + 1 * (size_t)Cc * Cc, bk, pK, 1);
    gemm_tf32<<<gg, 256, GEMM_SMEM>>>(pXc, pWc + 2 * (size_t)Cc * Cc, bv, pV, 0);

    zero_kv<<<(BH * Dd * Dd + 255) / 256, 256>>>();
    kv_accum<<<dim3(BH, KV_SPLIT), 256>>>();
    y_kernel<<<dim3(Tt / 64, BH), 256>>>();

    gemm_tf32<<<gg, 256, GEMM_SMEM>>>(pY, pWc + 3 * (size_t)Cc * Cc, bo, out, 0);
}

// round 6
// speedup vs baseline: 3.3416x; 1.3655x over previous
#include <cuda_runtime.h>
#include <cuda_fp16.h>
#include <math.h>
#include <stdint.h>

// ---------------- Problem constants ----------------
#define Bb 8
#define Tt 8192
#define Cc 512
#define Hh 8
#define Dd 64
#define NN (Bb*Tt)         // 65536 tokens
#define BH (Bb*Hh)         // 64
#define KV_SPLIT 8

// ---------------- Scratch (device globals) ----------------
__device__ __half g_Xh[(size_t)NN*Cc];
__device__ __half g_Wh[(size_t)4*Cc*Cc];
__device__ __half g_Qh[(size_t)NN*Cc];
__device__ __half g_Kh[(size_t)NN*Cc];
__device__ __half g_Vh[(size_t)NN*Cc];
__device__ __half g_Yh[(size_t)NN*Cc];
__device__ float  g_KV[(size_t)BH*Dd*Dd];
__device__ float  g_Ksum[(size_t)BH*Dd];

// ---------------- helpers ----------------
__device__ __forceinline__ uint32_t smem_u32(const void* p) {
    uint32_t a;
    asm("{ .reg .u64 t; cvta.to.shared.u64 t, %1; cvt.u32.u64 %0, t; }" : "=r"(a) : "l"(p));
    return a;
}
#define CP_ASYNC16(dst, src) \
    asm volatile("cp.async.cg.shared.global [%0], [%1], 16;" :: "r"(dst), "l"(src) : "memory")
#define CP_COMMIT() asm volatile("cp.async.commit_group;" ::: "memory")
#define CP_WAIT(n)  asm volatile("cp.async.wait_group %0;" :: "n"(n) : "memory")

__device__ __forceinline__ void ldsm_x4(uint32_t* r, uint32_t addr) {
    asm volatile("ldmatrix.sync.aligned.m8n8.x4.shared.b16 {%0,%1,%2,%3}, [%4];"
                 : "=r"(r[0]), "=r"(r[1]), "=r"(r[2]), "=r"(r[3]) : "r"(addr));
}
__device__ __forceinline__ void mma_f16(float* c, const uint32_t* a, uint32_t b0, uint32_t b1) {
    asm volatile("mma.sync.aligned.m16n8k16.row.col.f32.f16.f16.f32 "
                 "{%0,%1,%2,%3},{%4,%5,%6,%7},{%8,%9},{%0,%1,%2,%3};"
                 : "+f"(c[0]), "+f"(c[1]), "+f"(c[2]), "+f"(c[3])
                 : "r"(a[0]), "r"(a[1]), "r"(a[2]), "r"(a[3]), "r"(b0), "r"(b1));
}

// ---------------- GEMM config (fp16) ----------------
#define BM 128
#define BN 128
#define BKH 64                      // K halves per stage (128 B rows)
#define NKH (Cc / BKH)              // 8
#define ASTRH 72                    // padded row stride in halves
#define TILEH (BM * ASTRH)          // 9216 halves / operand
#define STAGEH (2 * TILEH)          // A + B
#define NSTG 3
#define GEMM_SMEM (NSTG * STAGEH * 2)   // 110592 bytes

// out[m, n] = sum_k A[m,k]*B[n,k] + bias[n]; act -> elu(v)+1; outHalf -> fp16 store
__global__ __launch_bounds__(256, 2)
void gemm_f16(const __half* __restrict__ A, const __half* __restrict__ B,
              const float* __restrict__ bias, void* __restrict__ outp,
              int act, int outHalf)
{
    extern __shared__ __half smh[];
    const int tid = threadIdx.x;
    const int wid = tid >> 5;
    const int lane = tid & 31;
    const int m0 = blockIdx.x * BM;
    const int n0 = blockIdx.y * BN;

    const int m_warp = (wid >> 2) * 64;
    const int n_warp = (wid & 3) * 32;

    // ldmatrix x4 addressing (thread group g8 = lane/8 picks matrix)
    const int g8 = lane >> 3;
    const int r8 = lane & 7;
    const int a_row_l = r8 + (g8 & 1) * 8;
    const int a_kb    = (g8 >> 1) * 16;
    const int b_row_l = r8 + (g8 >> 1) * 8;
    const int b_kb    = (g8 & 1) * 16;

    const uint32_t smb = smem_u32(smh);

    float acc[4][4][4];
#pragma unroll
    for (int i = 0; i < 4; i++)
#pragma unroll
        for (int j = 0; j < 4; j++)
#pragma unroll
            for (int k = 0; k < 4; k++) acc[i][j][k] = 0.f;

    auto load_stage = [&](int kc, int s) {
        const __half* gA = A + (size_t)m0 * Cc + kc * BKH;
        const __half* gB = B + (size_t)n0 * Cc + kc * BKH;
        uint32_t dA = smb + (uint32_t)(s * STAGEH) * 2;
        uint32_t dB = dA + (uint32_t)TILEH * 2;
#pragma unroll
        for (int i = 0; i < 4; i++) {
            int idx = tid + i * 256;         // 0..1023
            int row = idx >> 3;
            int c8 = idx & 7;                // 8-half (16 B) unit
            CP_ASYNC16(dA + (uint32_t)(row * ASTRH + c8 * 8) * 2, gA + (size_t)row * Cc + c8 * 8);
        }
#pragma unroll
        for (int i = 0; i < 4; i++) {
            int idx = tid + i * 256;
            int row = idx >> 3;
            int c8 = idx & 7;
            CP_ASYNC16(dB + (uint32_t)(row * ASTRH + c8 * 8) * 2, gB + (size_t)row * Cc + c8 * 8);
        }
        CP_COMMIT();
    };

    load_stage(0, 0);
    load_stage(1, 1);

    for (int kt = 0; kt < NKH; kt++) {
        if (kt < NKH - 1) CP_WAIT(1); else CP_WAIT(0);
        __syncthreads();                         // also guards WAR on stage (kt+2)%3
        if (kt + 2 < NKH) load_stage(kt + 2, (kt + 2) % 3);

        const int s = kt % 3;
        const uint32_t aB = smb + (uint32_t)(s * STAGEH) * 2
                          + (uint32_t)((m_warp + a_row_l) * ASTRH) * 2 + a_kb;
        const uint32_t bB = smb + (uint32_t)(s * STAGEH + TILEH) * 2
                          + (uint32_t)((n_warp + b_row_l) * ASTRH) * 2 + b_kb;

#pragma unroll
        for (int ks = 0; ks < 4; ks++) {         // 4 x k16 = 64
            uint32_t af[4][4];
#pragma unroll
            for (int mi = 0; mi < 4; mi++)
                ldsm_x4(af[mi], aB + (uint32_t)(mi * 16 * ASTRH) * 2 + ks * 32);
#pragma unroll
            for (int p = 0; p < 2; p++) {
                uint32_t bf[4];
                ldsm_x4(bf, bB + (uint32_t)(p * 16 * ASTRH) * 2 + ks * 32);
#pragma unroll
                for (int mi = 0; mi < 4; mi++) {
                    mma_f16(acc[mi][p * 2 + 0], af[mi], bf[0], bf[1]);
                    mma_f16(acc[mi][p * 2 + 1], af[mi], bf[2], bf[3]);
                }
            }
        }
    }

    // ---- epilogue: bias + optional ELU+1, f32 or f16 store ----
    const int r_lo = lane >> 2;
    const int c_off = (lane & 3) * 2;
#pragma unroll
    for (int mi = 0; mi < 4; mi++) {
#pragma unroll
        for (int nj = 0; nj < 4; nj++) {
            int col = n0 + n_warp + nj * 8 + c_off;
            float b0 = bias[col], b1 = bias[col + 1];
#pragma unroll
            for (int half_ = 0; half_ < 2; half_++) {
                int row = m0 + m_warp + mi * 16 + r_lo + half_ * 8;
                float v0 = acc[mi][nj][half_ * 2 + 0] + b0;
                float v1 = acc[mi][nj][half_ * 2 + 1] + b1;
                if (act) {
                    v0 = (v0 > 0.f) ? v0 + 1.f : expf(v0);
                    v1 = (v1 > 0.f) ? v1 + 1.f : expf(v1);
                }
                if (outHalf) {
                    __half2 hv = __floats2half2_rn(v0, v1);
                    *(__half2*)((__half*)outp + (size_t)row * Cc + col) = hv;
                } else {
                    *(float2*)((float*)outp + (size_t)row * Cc + col) = make_float2(v0, v1);
                }
            }
        }
    }
}

// ---------------- f32 -> f16 conversion ----------------
__global__ __launch_bounds__(256) void cvt_f16(const float4* __restrict__ src,
                                               uint4* __restrict__ dst, int n8)
{
    int i = blockIdx.x * blockDim.x + threadIdx.x;
    if (i < n8) {
        float4 a = src[2 * i], b = src[2 * i + 1];
        __half2 h0 = __floats2half2_rn(a.x, a.y);
        __half2 h1 = __floats2half2_rn(a.z, a.w);
        __half2 h2 = __floats2half2_rn(b.x, b.y);
        __half2 h3 = __floats2half2_rn(b.z, b.w);
        uint4 o;
        o.x = *(uint32_t*)&h0; o.y = *(uint32_t*)&h1;
        o.z = *(uint32_t*)&h2; o.w = *(uint32_t*)&h3;
        dst[i] = o;
    }
}

// ---------------- attention-side kernels ----------------
__global__ void zero_kv()
{
    int i = blockIdx.x * blockDim.x + threadIdx.x;
    if (i < BH * Dd * Dd) g_KV[i] = 0.f;
    if (i < BH * Dd)      g_Ksum[i] = 0.f;
}

__global__ __launch_bounds__(256) void kv_accum()
{
    const int bh = blockIdx.x;
    const int b = bh >> 3, h = bh & 7;
    const int tid = threadIdx.x;
    const int rows = Tt / KV_SPLIT;
    const size_t base = ((size_t)b * Tt + (size_t)blockIdx.y * rows) * Cc + h * Dd;

    __shared__ float sK[8][64];
    __shared__ float sV[8][64];

    const int d0 = (tid >> 4) * 4;
    const int e0 = (tid & 15) * 4;

    // loader coords: 256 threads = 8 rows x 32 half2 slots (exactly one tile)
    const int ld_r = tid >> 5;           // 0..7
    const int ld_p = (tid & 31) * 2;     // 0,2,..,62

    float acc[4][4];
#pragma unroll
    for (int i = 0; i < 4; i++)
#pragma unroll
        for (int j = 0; j < 4; j++) acc[i][j] = 0.f;
    float ks = 0.f;

    for (int r0 = 0; r0 < rows; r0 += 8) {
        {
            size_t g = base + (size_t)(r0 + ld_r) * Cc + ld_p;
            float2 kf = __half22float2(*(const __half2*)(g_Kh + g));
            float2 vf = __half22float2(*(const __half2*)(g_Vh + g));
            sK[ld_r][ld_p] = kf.x; sK[ld_r][ld_p + 1] = kf.y;
            sV[ld_r][ld_p] = vf.x; sV[ld_r][ld_p + 1] = vf.y;
        }
        __syncthreads();
#pragma unroll
        for (int r = 0; r < 8; r++) {
            float k0 = sK[r][d0], k1 = sK[r][d0 + 1], k2 = sK[r][d0 + 2], k3 = sK[r][d0 + 3];
            float v0 = sV[r][e0], v1 = sV[r][e0 + 1], v2 = sV[r][e0 + 2], v3 = sV[r][e0 + 3];
            acc[0][0] = fmaf(k0, v0, acc[0][0]); acc[0][1] = fmaf(k0, v1, acc[0][1]);
            acc[0][2] = fmaf(k0, v2, acc[0][2]); acc[0][3] = fmaf(k0, v3, acc[0][3]);
            acc[1][0] = fmaf(k1, v0, acc[1][0]); acc[1][1] = fmaf(k1, v1, acc[1][1]);
            acc[1][2] = fmaf(k1, v2, acc[1][2]); acc[1][3] = fmaf(k1, v3, acc[1][3]);
            acc[2][0] = fmaf(k2, v0, acc[2][0]); acc[2][1] = fmaf(k2, v1, acc[2][1]);
            acc[2][2] = fmaf(k2, v2, acc[2][2]); acc[2][3] = fmaf(k2, v3, acc[2][3]);
            acc[3][0] = fmaf(k3, v0, acc[3][0]); acc[3][1] = fmaf(k3, v1, acc[3][1]);
            acc[3][2] = fmaf(k3, v2, acc[3][2]); acc[3][3] = fmaf(k3, v3, acc[3][3]);
        }
        if (tid < 64) {
#pragma unroll
            for (int r = 0; r < 8; r++) ks += sK[r][tid];
        }
        __syncthreads();
    }

    float* kvp = g_KV + (size_t)bh * Dd * Dd;
#pragma unroll
    for (int i = 0; i < 4; i++)
#pragma unroll
        for (int j = 0; j < 4; j++)
            atomicAdd(&kvp[(d0 + i) * Dd + (e0 + j)], acc[i][j]);
    if (tid < 64) atomicAdd(&g_Ksum[bh * Dd + tid], ks);
}

__global__ __launch_bounds__(256) void y_kernel()
{
    const int bh = blockIdx.y;
    const int b = bh >> 3, h = bh & 7;
    const int t0 = blockIdx.x * 64;
    const int tid = threadIdx.x;

    __shared__ float sKV[64][64];
    __shared__ float sQ[64][65];
    __shared__ float sks[64];

    const float* kvp = g_KV + (size_t)bh * Dd * Dd;
#pragma unroll
    for (int i = 0; i < 16; i++) {
        int idx = tid + i * 256;
        sKV[idx >> 6][idx & 63] = kvp[idx];
    }
    if (tid < 64) sks[tid] = g_Ksum[bh * Dd + tid];
#pragma unroll
    for (int i = 0; i < 8; i++) {
        int idx = tid + i * 256;                 // 0..2047 half2 slots (64 rows x 32)
        int r = idx >> 5;                        // 0..63
        int d2 = (idx & 31) * 2;
        float2 qf = __half22float2(*(const __half2*)(
            g_Qh + ((size_t)b * Tt + t0 + r) * Cc + h * Dd + d2));
        sQ[r][d2] = qf.x; sQ[r][d2 + 1] = qf.y;
    }
    __syncthreads();

    const int tok = tid >> 2;
    const int e0 = (tid & 3) * 16;

    float acc[16];
#pragma unroll
    for (int j = 0; j < 16; j++) acc[j] = 0.f;
    float nrm = 0.f;

#pragma unroll
    for (int d = 0; d < 64; d++) {
        float q = sQ[tok][d];
        nrm = fmaf(q, sks[d], nrm);
        const float4* kr = (const float4*)&sKV[d][e0];
        float4 c0 = kr[0], c1 = kr[1], c2 = kr[2], c3 = kr[3];
        acc[0]  = fmaf(q, c0.x, acc[0]);  acc[1]  = fmaf(q, c0.y, acc[1]);
        acc[2]  = fmaf(q, c0.z, acc[2]);  acc[3]  = fmaf(q, c0.w, acc[3]);
        acc[4]  = fmaf(q, c1.x, acc[4]);  acc[5]  = fmaf(q, c1.y, acc[5]);
        acc[6]  = fmaf(q, c1.z, acc[6]);  acc[7]  = fmaf(q, c1.w, acc[7]);
        acc[8]  = fmaf(q, c2.x, acc[8]);  acc[9]  = fmaf(q, c2.y, acc[9]);
        acc[10] = fmaf(q, c2.z, acc[10]); acc[11] = fmaf(q, c2.w, acc[11]);
        acc[12] = fmaf(q, c3.x, acc[12]); acc[13] = fmaf(q, c3.y, acc[13]);
        acc[14] = fmaf(q, c3.z, acc[14]); acc[15] = fmaf(q, c3.w, acc[15]);
    }

    float inv = 1.f / (nrm + 1e-6f);
    size_t ob = ((size_t)b * Tt + t0 + tok) * Cc + h * Dd + e0;
#pragma unroll
    for (int j = 0; j < 16; j += 2) {
        __half2 hv = __floats2half2_rn(acc[j] * inv, acc[j + 1] * inv);
        *(__half2*)(g_Yh + ob + j) = hv;
    }
}

// ---------------- launch ----------------
extern "C" void kernel_launch(void* const* d_in, const int* in_sizes, int n_in,
                              void* d_out, int out_size)
{
    const float* x  = (const float*)d_in[0];
    const float* Wq = (const float*)d_in[1];
    const float* bq = (const float*)d_in[2];
    const float* Wk = (const float*)d_in[3];
    const float* bk = (const float*)d_in[4];
    const float* Wv = (const float*)d_in[5];
    const float* bv = (const float*)d_in[6];
    const float* Wo = (const float*)d_in[7];
    const float* bo = (const float*)d_in[8];
    float* out = (float*)d_out;

    static __half *pXh = nullptr, *pWh, *pQh, *pKh, *pVh, *pYh;
    static bool inited = false;
    if (!inited) {
        cudaGetSymbolAddress((void**)&pXh, g_Xh);
        cudaGetSymbolAddress((void**)&pWh, g_Wh);
        cudaGetSymbolAddress((void**)&pQh, g_Qh);
        cudaGetSymbolAddress((void**)&pKh, g_Kh);
        cudaGetSymbolAddress((void**)&pVh, g_Vh);
        cudaGetSymbolAddress((void**)&pYh, g_Yh);
        cudaFuncSetAttribute(gemm_f16, cudaFuncAttributeMaxDynamicSharedMemorySize, GEMM_SMEM);
        inited = true;
    }

    // f32 -> f16 conversion of GEMM inputs
    const float* Ws[4] = {Wq, Wk, Wv, Wo};
    {
        int n8 = NN * Cc / 8;
        cvt_f16<<<n8 / 256, 256>>>((const float4*)x, (uint4*)pXh, n8);
        int w8 = Cc * Cc / 8;
        for (int i = 0; i < 4; i++)
            cvt_f16<<<w8 / 256, 256>>>((const float4*)Ws[i], (uint4*)(pWh + (size_t)i * Cc * Cc), w8);
    }

    dim3 gg(NN / BM, Cc / BN);   // (512, 4)

    gemm_f16<<<gg, 256, GEMM_SMEM>>>(pXh, pWh + 0 * (size_t)Cc * Cc, bq, pQh, 1, 1);
    gemm_f16<<<gg, 256, GEMM_SMEM>>>(pXh, pWh + 1 * (size_t)Cc * Cc, bk, pKh, 1, 1);
    gemm_f16<<<gg, 256, GEMM_SMEM>>>(pXh, pWh + 2 * (size_t)Cc * Cc, bv, pVh, 0, 1);

    zero_kv<<<(BH * Dd * Dd + 255) / 256, 256>>>();
    kv_accum<<<dim3(BH, KV_SPLIT), 256>>>();
    y_kernel<<<dim3(Tt / 64, BH), 256>>>();

    gemm_f16<<<gg, 256, GEMM_SMEM>>>(pYh, pWh + 3 * (size_t)Cc * Cc, bo, out, 0, 0);
}